// round 11
// baseline (speedup 1.0000x reference)
#include <cuda_runtime.h>
#include <cuda_fp16.h>
#include <cstdint>

#define NB 8
#define LQ 256
#define LK 256
#define HH 256
#define DV 256
#define MASK_VALUE -1000000.0f

// Scratch (allocation-free rule: device globals)
__device__ float g_Qp[NB * LQ * HH];
__device__ float g_Kp[NB * LK * HH];
__device__ float g_S[NB * LQ * LK];         // scores, then attn (tf32-rounded)
__device__ uint32_t g_Vt[NB * DV * LK];     // V transposed + tf32: [b][d][k]

__device__ __forceinline__ uint32_t f2tf(float x) {
    uint32_t r;
    asm("cvt.rna.tf32.f32 %0, %1;" : "=r"(r) : "f"(x));
    return r;
}

__device__ __forceinline__ uint4 tf4(float4 v) {
    return make_uint4(f2tf(v.x), f2tf(v.y), f2tf(v.z), f2tf(v.w));
}

__device__ __forceinline__ __half2 tanh2(__half2 x) {
    uint32_t xi = *(uint32_t*)&x;
    uint32_t yi;
    asm("tanh.approx.f16x2 %0, %1;" : "=r"(yi) : "r"(xi));
    return *(__half2*)&yi;
}

// D += A(16x8,row) * B(8x8,col)  in tf32, fp32 accum
__device__ __forceinline__ void mma8(float* d, const uint32_t* a, const uint32_t* b) {
    asm("mma.sync.aligned.m16n8k8.row.col.f32.tf32.tf32.f32 "
        "{%0,%1,%2,%3}, {%4,%5,%6,%7}, {%8,%9}, {%0,%1,%2,%3};"
        : "+f"(d[0]), "+f"(d[1]), "+f"(d[2]), "+f"(d[3])
        : "r"(a[0]), "r"(a[1]), "r"(a[2]), "r"(a[3]), "r"(b[0]), "r"(b[1]));
}

#define TS 36  // smem stride, k-contiguous tiles (fragment LDS conflict-free)

// ---------------------------------------------------------------------------
// proj_kernel, grid (4, 64, 3), 128 threads:
//   z=0: g_Qp = queries @ W_q^T   (NT GEMM: 32m x 64n tiles, ONE wave)
//   z=1: g_Kp = keyes   @ W_k^T
//   z=2: g_Vt[b][d][k] = tf32(V[b][k][d])  (256 blocks x 2 tiles)
// ---------------------------------------------------------------------------
__global__ void __launch_bounds__(128) proj_kernel(
    const float* __restrict__ Xq, const float* __restrict__ Wq,
    const float* __restrict__ Xk, const float* __restrict__ Wk,
    const float* __restrict__ Vv) {
    __shared__ uint32_t sbuf[2 * 32 * TS + 2 * 64 * TS];  // 27648 B
    const int tid = threadIdx.x;

    if (blockIdx.z == 2) {
        // ---- V transpose+tf32: two 32x32 tiles per block ----
        float* ts = (float*)sbuf;   // [32][33]
        const int base_t = (blockIdx.y * 4 + blockIdx.x) * 2;
        for (int tt = 0; tt < 2; tt++) {
            const int t = base_t + tt;
            const int b = t >> 6;
            const int r = t & 63;
            const int k0 = (r >> 3) * 32;
            const int d0 = (r & 7) * 32;
            const float* V = Vv + b * LK * DV;
            #pragma unroll
            for (int j = 0; j < 2; j++) {
                int idx = tid + j * 128;
                int kr = idx >> 3, c4 = idx & 7;
                float4 v = *(const float4*)&V[(k0 + kr) * DV + d0 + c4 * 4];
                ts[(c4 * 4 + 0) * 33 + kr] = v.x;
                ts[(c4 * 4 + 1) * 33 + kr] = v.y;
                ts[(c4 * 4 + 2) * 33 + kr] = v.z;
                ts[(c4 * 4 + 3) * 33 + kr] = v.w;
            }
            __syncthreads();
            uint32_t* Vt = g_Vt + b * DV * LK;
            #pragma unroll
            for (int j = 0; j < 2; j++) {
                int idx = tid + j * 128;
                int dr = idx >> 3, c4 = idx & 7;
                const float* p = &ts[dr * 33 + c4 * 4];
                uint4 w = make_uint4(f2tf(p[0]), f2tf(p[1]), f2tf(p[2]), f2tf(p[3]));
                *(uint4*)&Vt[(d0 + dr) * LK + k0 + c4 * 4] = w;
            }
            __syncthreads();
        }
        return;
    }

    // ---- projection GEMM: 32m x 64n, 4 warps, warp tile 16m x 32n ----
    const float* X;
    const float* W;
    float* C;
    if (blockIdx.z == 0) { X = Xq; W = Wq; C = g_Qp; }
    else                 { X = Xk; W = Wk; C = g_Kp; }

    uint32_t* Xs = sbuf;                 // [2][32*TS]
    uint32_t* Ws = sbuf + 2 * 32 * TS;   // [2][64*TS]

    const int lane = tid & 31;
    const int warp = tid >> 5;
    const int gid = lane >> 2;
    const int tig = lane & 3;
    const int wm = (warp & 1) * 16;
    const int wn = (warp >> 1) * 32;
    const int m0 = blockIdx.y * 32;
    const int n0 = blockIdx.x * 64;

    float d[4][4];
    #pragma unroll
    for (int j = 0; j < 4; j++)
        #pragma unroll
        for (int e = 0; e < 4; e++) d[j][e] = 0.f;

    // staging coords: X 32x32 (2 float4/thr), W 64x32 (4 float4/thr)
    float4 xv[2], wv4[4];
    #pragma unroll
    for (int j = 0; j < 2; j++) {
        int idx = tid + j * 128;
        xv[j] = *(const float4*)&X[(m0 + (idx >> 3)) * 256 + (idx & 7) * 4];
    }
    #pragma unroll
    for (int j = 0; j < 4; j++) {
        int idx = tid + j * 128;
        wv4[j] = *(const float4*)&W[(n0 + (idx >> 3)) * 256 + (idx & 7) * 4];
    }

    for (int c = 0; c < 8; c++) {
        uint32_t* XB = Xs + (c & 1) * 32 * TS;
        uint32_t* WB = Ws + (c & 1) * 64 * TS;
        #pragma unroll
        for (int j = 0; j < 2; j++) {
            int idx = tid + j * 128;
            *(uint4*)&XB[(idx >> 3) * TS + (idx & 7) * 4] = tf4(xv[j]);
        }
        #pragma unroll
        for (int j = 0; j < 4; j++) {
            int idx = tid + j * 128;
            *(uint4*)&WB[(idx >> 3) * TS + (idx & 7) * 4] = tf4(wv4[j]);
        }
        __syncthreads();

        if (c < 7) {
            const int k0 = (c + 1) * 32;
            #pragma unroll
            for (int j = 0; j < 2; j++) {
                int idx = tid + j * 128;
                xv[j] = *(const float4*)&X[(m0 + (idx >> 3)) * 256 + k0 + (idx & 7) * 4];
            }
            #pragma unroll
            for (int j = 0; j < 4; j++) {
                int idx = tid + j * 128;
                wv4[j] = *(const float4*)&W[(n0 + (idx >> 3)) * 256 + k0 + (idx & 7) * 4];
            }
        }

        #pragma unroll
        for (int ks = 0; ks < 4; ks++) {
            const int kk = ks * 8;
            uint32_t a[4], b[4][2];
            const int r = wm + gid;
            a[0] = XB[r * TS + kk + tig];
            a[1] = XB[(r + 8) * TS + kk + tig];
            a[2] = XB[r * TS + kk + tig + 4];
            a[3] = XB[(r + 8) * TS + kk + tig + 4];
            #pragma unroll
            for (int jn = 0; jn < 4; jn++) {
                const int n = wn + jn * 8 + gid;
                b[jn][0] = WB[n * TS + kk + tig];
                b[jn][1] = WB[n * TS + kk + tig + 4];
            }
            #pragma unroll
            for (int jn = 0; jn < 4; jn++) mma8(d[jn], a, b[jn]);
        }
    }

    const int row = m0 + wm + gid;
    #pragma unroll
    for (int jn = 0; jn < 4; jn++) {
        const int col = n0 + wn + jn * 8 + tig * 2;
        *(float2*)&C[row * 256 + col] = make_float2(d[jn][0], d[jn][1]);
        *(float2*)&C[(row + 8) * 256 + col] = make_float2(d[jn][2], d[jn][3]);
    }
}

// ---------------------------------------------------------------------------
// Scores (fp16x2 tanh): S[b][q][k] = sum_h Wv[h]*tanh(Qp[b][q][h]+Kp[b][k][h])
// K packed in half2 pairs, Q duplicated in half2. Accumulation fp32.
// Masked 32x32 tiles skip all compute.
// ---------------------------------------------------------------------------
__global__ void scores_kernel(const float* __restrict__ Wv,
                              const int* __restrict__ vlens) {
    const int b = blockIdx.z;
    const int q0 = blockIdx.y * 32;
    const int k0 = blockIdx.x * 32;
    const int tid = threadIdx.x;
    const int tx = tid & 15;
    const int ty = tid >> 4;
    const int vl = vlens[b];
    float* S = g_S + b * LQ * LK;

    if (k0 >= vl) {
        const float2 mv = make_float2(MASK_VALUE, MASK_VALUE);
        #pragma unroll
        for (int i = 0; i < 2; i++)
            *(float2*)&S[(q0 + 2 * ty + i) * LK + k0 + 2 * tx] = mv;
        return;
    }

    __shared__ __half2 Qs[64][34];
    __shared__ __half2 Ks[64][18];
    __shared__ float sWv[256];

    sWv[tid] = Wv[tid];

    const float* Qb = g_Qp + (b * LQ + q0) * HH;
    const float* Kb = g_Kp + (b * LK + k0) * HH;

    float a00 = 0.f, a01 = 0.f, a10 = 0.f, a11 = 0.f;

    for (int h0 = 0; h0 < HH; h0 += 64) {
        #pragma unroll
        for (int j = 0; j < 8; j++) {
            int idx = tid + j * 256;
            int h = idx & 63;
            int qi = idx >> 6;
            Qs[h][qi] = __float2half2_rn(Qb[qi * HH + h0 + h]);
        }
        #pragma unroll
        for (int j = 0; j < 4; j++) {
            int idx = tid + j * 256;
            int h = idx & 63;
            int kj = idx >> 6;
            float ka = Kb[(2 * kj) * HH + h0 + h];
            float kb2 = Kb[(2 * kj + 1) * HH + h0 + h];
            Ks[h][kj] = __floats2half2_rn(ka, kb2);
        }
        __syncthreads();
        #pragma unroll 8
        for (int h = 0; h < 64; h++) {
            __half2 kp = Ks[h][tx];
            __half2 s0 = __hadd2(Qs[h][2 * ty], kp);
            __half2 s1 = __hadd2(Qs[h][2 * ty + 1], kp);
            float2 f0 = __half22float2(tanh2(s0));
            float2 f1 = __half22float2(tanh2(s1));
            float wv = sWv[h0 + h];
            a00 += wv * f0.x;
            a01 += wv * f0.y;
            a10 += wv * f1.x;
            a11 += wv * f1.y;
        }
        __syncthreads();
    }

    const int kA = k0 + 2 * tx;
    const int kB = kA + 1;
    const int qA = q0 + 2 * ty;
    const int qB = qA + 1;
    S[qA * LK + kA] = (kA < vl) ? a00 : MASK_VALUE;
    S[qA * LK + kB] = (kB < vl) ? a01 : MASK_VALUE;
    S[qB * LK + kA] = (kA < vl) ? a10 : MASK_VALUE;
    S[qB * LK + kB] = (kB < vl) ? a11 : MASK_VALUE;
}

// ---------------------------------------------------------------------------
// Softmax over axis=1 (QUERY axis) per (b, k) column — reference quirk.
// Writes attn pre-rounded to tf32 so out_kernel can stage with pure copies.
// ---------------------------------------------------------------------------
__global__ void softmax_kernel() {
    const int b = blockIdx.y;
    const int tx = threadIdx.x & 31;
    const int ty = threadIdx.x >> 5;
    const int k = blockIdx.x * 32 + tx;
    float* S = g_S + b * LQ * LK;

    float vals[32];
    float m = -3.4e38f;
    #pragma unroll
    for (int i = 0; i < 32; i++) {
        vals[i] = S[(i * 8 + ty) * LK + k];
        m = fmaxf(m, vals[i]);
    }

    __shared__ float red[8][33];
    red[ty][tx] = m;
    __syncthreads();
    float M = red[0][tx];
    #pragma unroll
    for (int t = 1; t < 8; t++) M = fmaxf(M, red[t][tx]);
    __syncthreads();

    float s = 0.f;
    #pragma unroll
    for (int i = 0; i < 32; i++) {
        vals[i] = __expf(vals[i] - M);
        s += vals[i];
    }
    red[ty][tx] = s;
    __syncthreads();
    float SUM = 0.f;
    #pragma unroll
    for (int t = 0; t < 8; t++) SUM += red[t][tx];

    const float inv = 1.0f / SUM;
    #pragma unroll
    for (int i = 0; i < 32; i++)
        S[(i * 8 + ty) * LK + k] = __uint_as_float(f2tf(vals[i] * inv));
}

// ---------------------------------------------------------------------------
// Output NN GEMM (tf32): out[b][q][d] = sum_k A[b][q][k]*Vt[b][d][k]
// CTA 32q x 32d, 4 warps (2x2), warp tile 16x16; BOTH operands pre-tf32 in
// global -> staging is pure uint4 copies (no cvt, no transpose conflicts).
// grid (8, 8, 8) = 512 blocks.
// ---------------------------------------------------------------------------
__global__ void __launch_bounds__(128) out_kernel(float* __restrict__ out) {
    const int b = blockIdx.z;
    const int q0 = blockIdx.y * 32;
    const int d0 = blockIdx.x * 32;
    const int tid = threadIdx.x;
    const int lane = tid & 31;
    const int warp = tid >> 5;
    const int gid = lane >> 2;
    const int tig = lane & 3;
    const int wq = (warp & 1) * 16;
    const int wn = (warp >> 1) * 16;

    const uint32_t* A = (const uint32_t*)(g_S + b * LQ * LK);
    const uint32_t* Vt = g_Vt + b * DV * LK;

    __shared__ uint32_t As[2][32 * TS];
    __shared__ uint32_t Vs[2][32 * TS];

    float d[2][4] = {};

    uint4 av[2], vv[2];
    #pragma unroll
    for (int j = 0; j < 2; j++) {
        int idx = tid + j * 128;
        av[j] = *(const uint4*)&A[(q0 + (idx >> 3)) * LK + (idx & 7) * 4];
        vv[j] = *(const uint4*)&Vt[(d0 + (idx >> 3)) * LK + (idx & 7) * 4];
    }

    for (int c = 0; c < 8; c++) {
        uint32_t* AB = As[c & 1];
        uint32_t* VB = Vs[c & 1];
        #pragma unroll
        for (int j = 0; j < 2; j++) {
            int idx = tid + j * 128;
            *(uint4*)&AB[(idx >> 3) * TS + (idx & 7) * 4] = av[j];
            *(uint4*)&VB[(idx >> 3) * TS + (idx & 7) * 4] = vv[j];
        }
        __syncthreads();

        if (c < 7) {
            const int k0 = (c + 1) * 32;
            #pragma unroll
            for (int j = 0; j < 2; j++) {
                int idx = tid + j * 128;
                av[j] = *(const uint4*)&A[(q0 + (idx >> 3)) * LK + k0 + (idx & 7) * 4];
                vv[j] = *(const uint4*)&Vt[(d0 + (idx >> 3)) * LK + k0 + (idx & 7) * 4];
            }
        }

        #pragma unroll
        for (int ks = 0; ks < 4; ks++) {
            const int kk = ks * 8;
            uint32_t a[4], bfr[2][2];
            const int r = wq + gid;
            a[0] = AB[r * TS + kk + tig];
            a[1] = AB[(r + 8) * TS + kk + tig];
            a[2] = AB[r * TS + kk + tig + 4];
            a[3] = AB[(r + 8) * TS + kk + tig + 4];
            #pragma unroll
            for (int jn = 0; jn < 2; jn++) {
                const int n = wn + jn * 8 + gid;
                bfr[jn][0] = VB[n * TS + kk + tig];
                bfr[jn][1] = VB[n * TS + kk + tig + 4];
            }
            mma8(d[0], a, bfr[0]);
            mma8(d[1], a, bfr[1]);
        }
    }

    float* O = out + b * LQ * DV;
    #pragma unroll
    for (int jn = 0; jn < 2; jn++) {
        const int row = q0 + wq + gid;
        const int col = d0 + wn + jn * 8 + tig * 2;
        *(float2*)&O[row * DV + col] = make_float2(d[jn][0], d[jn][1]);
        *(float2*)&O[(row + 8) * DV + col] = make_float2(d[jn][2], d[jn][3]);
    }
}

extern "C" void kernel_launch(void* const* d_in, const int* in_sizes, int n_in,
                              void* d_out, int out_size) {
    const float* queries    = (const float*)d_in[0];
    const float* keyes      = (const float*)d_in[1];
    const float* values     = (const float*)d_in[2];
    const int*   valid_lens = (const int*)d_in[3];
    const float* W_q        = (const float*)d_in[4];
    const float* W_k        = (const float*)d_in[5];
    const float* W_v        = (const float*)d_in[6];
    float* out = (float*)d_out;

    proj_kernel<<<dim3(4, 64, 3), 128>>>(queries, W_q, keyes, W_k, values);
    scores_kernel<<<dim3(8, 8, 8), 256>>>(W_v, valid_lens);
    softmax_kernel<<<dim3(8, 8), 256>>>();
    out_kernel<<<dim3(8, 8, 8), 128>>>(out);
}

// round 12
// speedup vs baseline: 1.0335x; 1.0335x over previous
#include <cuda_runtime.h>
#include <cuda_fp16.h>
#include <cstdint>

#define NB 8
#define LQ 256
#define LK 256
#define HH 256
#define DV 256
#define MASK_VALUE -1000000.0f

// Scratch (allocation-free rule: device globals)
__device__ float g_Qp[NB * LQ * HH];
__device__ float g_Kp[NB * LK * HH];
__device__ float g_S[NB * LQ * LK];

__device__ __forceinline__ uint32_t f2tf(float x) {
    uint32_t r;
    asm("cvt.rna.tf32.f32 %0, %1;" : "=r"(r) : "f"(x));
    return r;
}

__device__ __forceinline__ __half2 tanh2(__half2 x) {
    uint32_t xi = *(uint32_t*)&x;
    uint32_t yi;
    asm("tanh.approx.f16x2 %0, %1;" : "=r"(yi) : "r"(xi));
    return *(__half2*)&yi;
}

// D += A(16x8,row) * B(8x8,col)  in tf32, fp32 accum
__device__ __forceinline__ void mma8(float* d, const uint32_t* a, const uint32_t* b) {
    asm("mma.sync.aligned.m16n8k8.row.col.f32.tf32.tf32.f32 "
        "{%0,%1,%2,%3}, {%4,%5,%6,%7}, {%8,%9}, {%0,%1,%2,%3};"
        : "+f"(d[0]), "+f"(d[1]), "+f"(d[2]), "+f"(d[3])
        : "r"(a[0]), "r"(a[1]), "r"(a[2]), "r"(a[3]), "r"(b[0]), "r"(b[1]));
}

#define TS 36  // smem stride, k-contiguous tiles (fragment LDS conflict-free)
#define VS 35  // smem stride, transposed V tile (<=2-way)

// ---------------------------------------------------------------------------
// Projection NT GEMM (tf32, R5/R9 structure): C[m][n] = sum_k X[m][k]*W[n][k]
// CTA 64m x 64n, 4 warps (2x2) of 32x32 warp tiles; kc=32, double-buffered.
// grid (4, 32, 2) = 256 blocks.
// ---------------------------------------------------------------------------
__global__ void __launch_bounds__(128) proj_kernel(
    const float* __restrict__ Xq, const float* __restrict__ Wq,
    const float* __restrict__ Xk, const float* __restrict__ Wk) {
    const float* X;
    const float* W;
    float* C;
    if (blockIdx.z == 0) { X = Xq; W = Wq; C = g_Qp; }
    else                 { X = Xk; W = Wk; C = g_Kp; }

    __shared__ uint32_t Xs[2][64 * TS];
    __shared__ uint32_t Ws[2][64 * TS];

    const int tid = threadIdx.x;
    const int lane = tid & 31;
    const int warp = tid >> 5;
    const int gid = lane >> 2;
    const int tig = lane & 3;
    const int wm = (warp & 1) * 32;
    const int wn = (warp >> 1) * 32;
    const int m0 = blockIdx.y * 64;
    const int n0 = blockIdx.x * 64;

    int srow[4], sc4[4];
    #pragma unroll
    for (int j = 0; j < 4; j++) {
        int idx = tid + j * 128;
        srow[j] = idx >> 3;
        sc4[j]  = idx & 7;
    }

    float d[2][4][4];
    #pragma unroll
    for (int i = 0; i < 2; i++)
        #pragma unroll
        for (int j = 0; j < 4; j++)
            #pragma unroll
            for (int e = 0; e < 4; e++) d[i][j][e] = 0.f;

    float4 xv[4], wv[4];
    #pragma unroll
    for (int j = 0; j < 4; j++) {
        xv[j] = *(const float4*)&X[(m0 + srow[j]) * 256 + sc4[j] * 4];
        wv[j] = *(const float4*)&W[(n0 + srow[j]) * 256 + sc4[j] * 4];
    }

    for (int c = 0; c < 8; c++) {
        uint32_t* XB = Xs[c & 1];
        uint32_t* WB = Ws[c & 1];
        #pragma unroll
        for (int j = 0; j < 4; j++) {
            uint32_t* px = &XB[srow[j] * TS + sc4[j] * 4];
            px[0] = f2tf(xv[j].x); px[1] = f2tf(xv[j].y);
            px[2] = f2tf(xv[j].z); px[3] = f2tf(xv[j].w);
            uint32_t* pw = &WB[srow[j] * TS + sc4[j] * 4];
            pw[0] = f2tf(wv[j].x); pw[1] = f2tf(wv[j].y);
            pw[2] = f2tf(wv[j].z); pw[3] = f2tf(wv[j].w);
        }
        __syncthreads();

        if (c < 7) {
            const int k0 = (c + 1) * 32;
            #pragma unroll
            for (int j = 0; j < 4; j++) {
                xv[j] = *(const float4*)&X[(m0 + srow[j]) * 256 + k0 + sc4[j] * 4];
                wv[j] = *(const float4*)&W[(n0 + srow[j]) * 256 + k0 + sc4[j] * 4];
            }
        }

        #pragma unroll
        for (int ks = 0; ks < 4; ks++) {
            const int kk = ks * 8;
            uint32_t a[2][4], b[4][2];
            #pragma unroll
            for (int i = 0; i < 2; i++) {
                int r = wm + i * 16 + gid;
                a[i][0] = XB[r * TS + kk + tig];
                a[i][1] = XB[(r + 8) * TS + kk + tig];
                a[i][2] = XB[r * TS + kk + tig + 4];
                a[i][3] = XB[(r + 8) * TS + kk + tig + 4];
            }
            #pragma unroll
            for (int jn = 0; jn < 4; jn++) {
                int n = wn + jn * 8 + gid;
                b[jn][0] = WB[n * TS + kk + tig];
                b[jn][1] = WB[n * TS + kk + tig + 4];
            }
            #pragma unroll
            for (int i = 0; i < 2; i++)
                #pragma unroll
                for (int jn = 0; jn < 4; jn++) mma8(d[i][jn], a[i], b[jn]);
        }
    }

    #pragma unroll
    for (int i = 0; i < 2; i++)
        #pragma unroll
        for (int jn = 0; jn < 4; jn++) {
            int row = m0 + wm + i * 16 + gid;
            int col = n0 + wn + jn * 8 + tig * 2;
            *(float2*)&C[row * 256 + col] = make_float2(d[i][jn][0], d[i][jn][1]);
            *(float2*)&C[(row + 8) * 256 + col] = make_float2(d[i][jn][2], d[i][jn][3]);
        }
}

// ---------------------------------------------------------------------------
// FUSED attn kernel: scores (f16x2 tanh) + softmax over the QUERY axis.
// Block = (8 k-columns, ALL 256 q) so softmax over q is block-local.
// grid (32 kblocks, 8 b), 256 threads, dynamic smem.
//   S[q][k]    = sum_h Wv[h]*tanh(Qp[q][h]+Kp[k][h])
//   attn[:,k]  = softmax_q(S[:,k]); masked column (k>=vl) -> uniform 1/256.
// ---------------------------------------------------------------------------
#define QS_STRIDE 33     // Qsm [256 h][33 q-slots] half2
#define KS_STRIDE 260    // Ksm [4 kp][260 h] half2
#define SC_STRIDE 260    // Scol/Part [8 k][260 q] float
#define ATTN_SMEM (256 * QS_STRIDE * 4 + 4 * KS_STRIDE * 4 + 2 * 8 * SC_STRIDE * 4 + 256 * 4)

extern __shared__ unsigned char attn_raw[];

__global__ void __launch_bounds__(256) attn_kernel(
    const float* __restrict__ Wv, const int* __restrict__ vlens) {
    const int b = blockIdx.y;
    const int k0 = blockIdx.x * 8;
    const int tid = threadIdx.x;
    const int lane = tid & 31;
    const int vl = vlens[b];
    float* S = g_S + b * LQ * LK;

    if (k0 >= vl) {
        // whole block masked: softmax over q of constant -> uniform 1/256
        const float u = 1.0f / 256.0f;
        float4 uu = make_float4(u, u, u, u);
        float* row = &S[tid * LK + k0];
        *(float4*)row = uu;
        *(float4*)(row + 4) = uu;
        return;
    }

    __half2* Qsm = (__half2*)attn_raw;                                   // [256h][33]
    __half2* Ksm = (__half2*)(attn_raw + 256 * QS_STRIDE * 4);           // [4kp][260]
    float* Scol  = (float*)(attn_raw + 256 * QS_STRIDE * 4 + 4 * KS_STRIDE * 4);
    float* Part  = Scol + 8 * SC_STRIDE;
    float* sWv   = Part + 8 * SC_STRIDE;

    sWv[tid] = Wv[tid];

    // stage K pairs (full K): kp = tid>>6, t63 = tid&63, h = t63 + 64j
    {
        const int kp = tid >> 6;
        const int t63 = tid & 63;
        const float* Kr0 = g_Kp + (b * LK + k0 + 2 * kp) * HH;
        const float* Kr1 = Kr0 + HH;
        #pragma unroll
        for (int j = 0; j < 4; j++) {
            int h = t63 + 64 * j;
            Ksm[kp * KS_STRIDE + h] = __floats2half2_rn(Kr0[h], Kr1[h]);
        }
    }
    __syncthreads();

    const int cq = tid & 31;          // q within tile
    const int ckp = (tid >> 5) & 3;   // k-pair 0..3
    const int chh = tid >> 7;         // h half 0/1
    const int h0 = chh * 128;
    const __half2* Kp = &Ksm[ckp * KS_STRIDE];

    for (int qt = 0; qt < 8; qt++) {
        const int q0 = qt * 32;
        // stage Q dup: qrow = tid>>3, hc = tid&7, float4 at h4 = hc + 8j
        {
            const int qrow = tid >> 3;
            const int hc = tid & 7;
            const float* Qr = g_Qp + (b * LQ + q0 + qrow) * HH;
            #pragma unroll
            for (int j = 0; j < 8; j++) {
                int h = (hc + j * 8) * 4;
                float4 qv = *(const float4*)&Qr[h];
                Qsm[(h + 0) * QS_STRIDE + qrow] = __float2half2_rn(qv.x);
                Qsm[(h + 1) * QS_STRIDE + qrow] = __float2half2_rn(qv.y);
                Qsm[(h + 2) * QS_STRIDE + qrow] = __float2half2_rn(qv.z);
                Qsm[(h + 3) * QS_STRIDE + qrow] = __float2half2_rn(qv.w);
            }
        }
        __syncthreads();

        float a0 = 0.f, a1 = 0.f;
        #pragma unroll 8
        for (int hi = 0; hi < 128; hi++) {
            const int h = h0 + hi;
            __half2 qd = Qsm[h * QS_STRIDE + cq];
            __half2 kv = Kp[h];
            float2 f = __half22float2(tanh2(__hadd2(qd, kv)));
            float wv = sWv[h];
            a0 += wv * f.x;
            a1 += wv * f.y;
        }
        float* dst = chh ? Part : Scol;
        dst[(2 * ckp) * SC_STRIDE + q0 + cq] = a0;
        dst[(2 * ckp + 1) * SC_STRIDE + q0 + cq] = a1;
        __syncthreads();
    }

    // merge h-halves: 2048 values, 8 per thread
    #pragma unroll
    for (int j = 0; j < 8; j++) {
        int i = tid + j * 256;
        int kk = i >> 8, qq = i & 255;
        Scol[kk * SC_STRIDE + qq] += Part[kk * SC_STRIDE + qq];
    }
    __syncthreads();

    // softmax per column: warp w -> column k0+w
    {
        const int w = tid >> 5;
        const int k = k0 + w;
        float vals[8];
        if (k >= vl) {
            #pragma unroll
            for (int j = 0; j < 8; j++) vals[j] = 1.0f / 256.0f;
        } else {
            float m = -3.4e38f;
            #pragma unroll
            for (int j = 0; j < 8; j++) {
                vals[j] = Scol[w * SC_STRIDE + lane + 32 * j];
                m = fmaxf(m, vals[j]);
            }
            #pragma unroll
            for (int o = 16; o > 0; o >>= 1)
                m = fmaxf(m, __shfl_xor_sync(0xffffffffu, m, o));
            float s = 0.f;
            #pragma unroll
            for (int j = 0; j < 8; j++) {
                vals[j] = __expf(vals[j] - m);
                s += vals[j];
            }
            #pragma unroll
            for (int o = 16; o > 0; o >>= 1)
                s += __shfl_xor_sync(0xffffffffu, s, o);
            const float inv = 1.0f / s;
            #pragma unroll
            for (int j = 0; j < 8; j++) vals[j] *= inv;
        }
        #pragma unroll
        for (int j = 0; j < 8; j++)
            Scol[w * SC_STRIDE + lane + 32 * j] = vals[j];
    }
    __syncthreads();

    // coalesced write: thread = q row, 8 contiguous k
    {
        float tmp[8];
        #pragma unroll
        for (int kk = 0; kk < 8; kk++) tmp[kk] = Scol[kk * SC_STRIDE + tid];
        float* row = &S[tid * LK + k0];
        *(float4*)row = make_float4(tmp[0], tmp[1], tmp[2], tmp[3]);
        *(float4*)(row + 4) = make_float4(tmp[4], tmp[5], tmp[6], tmp[7]);
    }
}

// ---------------------------------------------------------------------------
// Output NN GEMM (tf32, R6/R9 structure): out[b][q][d] = sum_k A[q][k]*V[k][d]
// CTA 32q x 32d, 4 warps (2x2), warp tile 16x16; V staged transposed [d][k].
// grid (8, 8, 8) = 512 blocks.
// ---------------------------------------------------------------------------
__global__ void __launch_bounds__(128) out_kernel(
    const float* __restrict__ Vv, float* __restrict__ out) {
    const int b = blockIdx.z;
    const int q0 = blockIdx.y * 32;
    const int d0 = blockIdx.x * 32;
    const int tid = threadIdx.x;
    const int lane = tid & 31;
    const int warp = tid >> 5;
    const int gid = lane >> 2;
    const int tig = lane & 3;
    const int wq = (warp & 1) * 16;
    const int wn = (warp >> 1) * 16;

    const float* A = g_S + b * LQ * LK;
    const float* V = Vv + b * LK * DV;

    __shared__ uint32_t As[2][32 * TS];
    __shared__ uint32_t Vs[2][32 * VS];

    int srow[2], sc4[2];
    #pragma unroll
    for (int j = 0; j < 2; j++) {
        int idx = tid + j * 128;
        srow[j] = idx >> 3;
        sc4[j]  = idx & 7;
    }

    float d[2][4] = {};

    float4 av[2], vv[2];
    #pragma unroll
    for (int j = 0; j < 2; j++) {
        av[j] = *(const float4*)&A[(q0 + srow[j]) * LK + sc4[j] * 4];
        vv[j] = *(const float4*)&V[srow[j] * DV + d0 + sc4[j] * 4];
    }

    for (int c = 0; c < 8; c++) {
        uint32_t* AB = As[c & 1];
        uint32_t* VB = Vs[c & 1];
        #pragma unroll
        for (int j = 0; j < 2; j++) {
            uint32_t* pa = &AB[srow[j] * TS + sc4[j] * 4];
            pa[0] = f2tf(av[j].x); pa[1] = f2tf(av[j].y);
            pa[2] = f2tf(av[j].z); pa[3] = f2tf(av[j].w);
            const int dc = sc4[j] * 4;
            VB[(dc + 0) * VS + srow[j]] = f2tf(vv[j].x);
            VB[(dc + 1) * VS + srow[j]] = f2tf(vv[j].y);
            VB[(dc + 2) * VS + srow[j]] = f2tf(vv[j].z);
            VB[(dc + 3) * VS + srow[j]] = f2tf(vv[j].w);
        }
        __syncthreads();

        if (c < 7) {
            const int k0 = (c + 1) * 32;
            #pragma unroll
            for (int j = 0; j < 2; j++) {
                av[j] = *(const float4*)&A[(q0 + srow[j]) * LK + k0 + sc4[j] * 4];
                vv[j] = *(const float4*)&V[(k0 + srow[j]) * DV + d0 + sc4[j] * 4];
            }
        }

        #pragma unroll
        for (int ks = 0; ks < 4; ks++) {
            const int kk = ks * 8;
            uint32_t a[4], bfr[2][2];
            const int r = wq + gid;
            a[0] = AB[r * TS + kk + tig];
            a[1] = AB[(r + 8) * TS + kk + tig];
            a[2] = AB[r * TS + kk + tig + 4];
            a[3] = AB[(r + 8) * TS + kk + tig + 4];
            #pragma unroll
            for (int jn = 0; jn < 2; jn++) {
                int n = wn + jn * 8 + gid;
                bfr[jn][0] = VB[n * VS + kk + tig];
                bfr[jn][1] = VB[n * VS + kk + tig + 4];
            }
            mma8(d[0], a, bfr[0]);
            mma8(d[1], a, bfr[1]);
        }
    }

    float* O = out + b * LQ * DV;
    #pragma unroll
    for (int jn = 0; jn < 2; jn++) {
        int row = q0 + wq + gid;
        int col = d0 + wn + jn * 8 + tig * 2;
        *(float2*)&O[row * DV + col] = make_float2(d[jn][0], d[jn][1]);
        *(float2*)&O[(row + 8) * DV + col] = make_float2(d[jn][2], d[jn][3]);
    }
}

extern "C" void kernel_launch(void* const* d_in, const int* in_sizes, int n_in,
                              void* d_out, int out_size) {
    const float* queries    = (const float*)d_in[0];
    const float* keyes      = (const float*)d_in[1];
    const float* values     = (const float*)d_in[2];
    const int*   valid_lens = (const int*)d_in[3];
    const float* W_q        = (const float*)d_in[4];
    const float* W_k        = (const float*)d_in[5];
    const float* W_v        = (const float*)d_in[6];
    float* out = (float*)d_out;

    cudaFuncSetAttribute(attn_kernel, cudaFuncAttributeMaxDynamicSharedMemorySize, ATTN_SMEM);

    proj_kernel<<<dim3(4, 32, 2), 128>>>(queries, W_q, keyes, W_k);
    attn_kernel<<<dim3(32, 8), 256, ATTN_SMEM>>>(W_v, valid_lens);
    out_kernel<<<dim3(8, 8, 8), 128>>>(values, out);
}

// round 13
// speedup vs baseline: 1.2426x; 1.2024x over previous
#include <cuda_runtime.h>
#include <cuda_fp16.h>
#include <cstdint>

#define NB 8
#define LQ 256
#define LK 256
#define HH 256
#define DV 256
#define MASK_VALUE -1000000.0f

// Scratch (allocation-free rule: device globals)
__device__ float g_Qp[NB * LQ * HH];
__device__ float g_Kp[NB * LK * HH];
__device__ float g_S[NB * LQ * LK];

__device__ __forceinline__ uint32_t f2tf(float x) {
    uint32_t r;
    asm("cvt.rna.tf32.f32 %0, %1;" : "=r"(r) : "f"(x));
    return r;
}

__device__ __forceinline__ uint32_t h2u(__half2 h) { return *(uint32_t*)&h; }

__device__ __forceinline__ uint32_t tanh2u(uint32_t x) {
    uint32_t y;
    asm("tanh.approx.f16x2 %0, %1;" : "=r"(y) : "r"(x));
    return y;
}

__device__ __forceinline__ uint32_t hadd2u(uint32_t a, uint32_t b) {
    uint32_t r;
    asm("add.rn.f16x2 %0, %1, %2;" : "=r"(r) : "r"(a), "r"(b));
    return r;
}

// D += A(16x8,row) * B(8x8,col)  in tf32, fp32 accum
__device__ __forceinline__ void mma8(float* d, const uint32_t* a, const uint32_t* b) {
    asm("mma.sync.aligned.m16n8k8.row.col.f32.tf32.tf32.f32 "
        "{%0,%1,%2,%3}, {%4,%5,%6,%7}, {%8,%9}, {%0,%1,%2,%3};"
        : "+f"(d[0]), "+f"(d[1]), "+f"(d[2]), "+f"(d[3])
        : "r"(a[0]), "r"(a[1]), "r"(a[2]), "r"(a[3]), "r"(b[0]), "r"(b[1]));
}

// D += A(16x16 f16,row) * B(16x8 f16,col), fp32 accum
__device__ __forceinline__ void mma16816(float* d, uint32_t a0, uint32_t a1,
                                         uint32_t a2, uint32_t a3,
                                         uint32_t b0, uint32_t b1) {
    asm("mma.sync.aligned.m16n8k16.row.col.f32.f16.f16.f32 "
        "{%0,%1,%2,%3}, {%4,%5,%6,%7}, {%8,%9}, {%0,%1,%2,%3};"
        : "+f"(d[0]), "+f"(d[1]), "+f"(d[2]), "+f"(d[3])
        : "r"(a0), "r"(a1), "r"(a2), "r"(a3), "r"(b0), "r"(b1));
}

#define TS 36  // smem stride, k-contiguous tf32 tiles (fragment LDS conflict-free)
#define VS 35  // smem stride, transposed V tile (<=2-way)
#define SQ 132 // scores smem stride in half2 units: 132%32==4 -> conflict-free frags

// ---------------------------------------------------------------------------
// Projection NT GEMM (tf32, R5/R9 structure): C[m][n] = sum_k X[m][k]*W[n][k]
// CTA 64m x 64n, 4 warps (2x2) of 32x32 warp tiles; kc=32, double-buffered.
// grid (4, 32, 2) = 256 blocks.
// ---------------------------------------------------------------------------
__global__ void __launch_bounds__(128) proj_kernel(
    const float* __restrict__ Xq, const float* __restrict__ Wq,
    const float* __restrict__ Xk, const float* __restrict__ Wk) {
    const float* X;
    const float* W;
    float* C;
    if (blockIdx.z == 0) { X = Xq; W = Wq; C = g_Qp; }
    else                 { X = Xk; W = Wk; C = g_Kp; }

    __shared__ uint32_t Xs[2][64 * TS];
    __shared__ uint32_t Ws[2][64 * TS];

    const int tid = threadIdx.x;
    const int lane = tid & 31;
    const int warp = tid >> 5;
    const int gid = lane >> 2;
    const int tig = lane & 3;
    const int wm = (warp & 1) * 32;
    const int wn = (warp >> 1) * 32;
    const int m0 = blockIdx.y * 64;
    const int n0 = blockIdx.x * 64;

    int srow[4], sc4[4];
    #pragma unroll
    for (int j = 0; j < 4; j++) {
        int idx = tid + j * 128;
        srow[j] = idx >> 3;
        sc4[j]  = idx & 7;
    }

    float d[2][4][4];
    #pragma unroll
    for (int i = 0; i < 2; i++)
        #pragma unroll
        for (int j = 0; j < 4; j++)
            #pragma unroll
            for (int e = 0; e < 4; e++) d[i][j][e] = 0.f;

    float4 xv[4], wv[4];
    #pragma unroll
    for (int j = 0; j < 4; j++) {
        xv[j] = *(const float4*)&X[(m0 + srow[j]) * 256 + sc4[j] * 4];
        wv[j] = *(const float4*)&W[(n0 + srow[j]) * 256 + sc4[j] * 4];
    }

    for (int c = 0; c < 8; c++) {
        uint32_t* XB = Xs[c & 1];
        uint32_t* WB = Ws[c & 1];
        #pragma unroll
        for (int j = 0; j < 4; j++) {
            uint32_t* px = &XB[srow[j] * TS + sc4[j] * 4];
            px[0] = f2tf(xv[j].x); px[1] = f2tf(xv[j].y);
            px[2] = f2tf(xv[j].z); px[3] = f2tf(xv[j].w);
            uint32_t* pw = &WB[srow[j] * TS + sc4[j] * 4];
            pw[0] = f2tf(wv[j].x); pw[1] = f2tf(wv[j].y);
            pw[2] = f2tf(wv[j].z); pw[3] = f2tf(wv[j].w);
        }
        __syncthreads();

        if (c < 7) {
            const int k0 = (c + 1) * 32;
            #pragma unroll
            for (int j = 0; j < 4; j++) {
                xv[j] = *(const float4*)&X[(m0 + srow[j]) * 256 + k0 + sc4[j] * 4];
                wv[j] = *(const float4*)&W[(n0 + srow[j]) * 256 + k0 + sc4[j] * 4];
            }
        }

        #pragma unroll
        for (int ks = 0; ks < 4; ks++) {
            const int kk = ks * 8;
            uint32_t a[2][4], b[4][2];
            #pragma unroll
            for (int i = 0; i < 2; i++) {
                int r = wm + i * 16 + gid;
                a[i][0] = XB[r * TS + kk + tig];
                a[i][1] = XB[(r + 8) * TS + kk + tig];
                a[i][2] = XB[r * TS + kk + tig + 4];
                a[i][3] = XB[(r + 8) * TS + kk + tig + 4];
            }
            #pragma unroll
            for (int jn = 0; jn < 4; jn++) {
                int n = wn + jn * 8 + gid;
                b[jn][0] = WB[n * TS + kk + tig];
                b[jn][1] = WB[n * TS + kk + tig + 4];
            }
            #pragma unroll
            for (int i = 0; i < 2; i++)
                #pragma unroll
                for (int jn = 0; jn < 4; jn++) mma8(d[i][jn], a[i], b[jn]);
        }
    }

    #pragma unroll
    for (int i = 0; i < 2; i++)
        #pragma unroll
        for (int jn = 0; jn < 4; jn++) {
            int row = m0 + wm + i * 16 + gid;
            int col = n0 + wn + jn * 8 + tig * 2;
            *(float2*)&C[row * 256 + col] = make_float2(d[i][jn][0], d[i][jn][1]);
            *(float2*)&C[(row + 8) * 256 + col] = make_float2(d[i][jn][2], d[i][jn][3]);
        }
}

// ---------------------------------------------------------------------------
// Scores via HMMA-accumulation:
//   S[q][k] = sum_h Wv[h] * tanh(Qp[q][h] + Kp[k][h])
// mma.m16n8k16.f16.f32 with rows = 16 k-values (fixed q), B = Wv replicated
// across all 8 columns -> every D column holds the desired h-sum in fp32.
// The hot loop is ONLY: LDS + HADD2 + tanh2 + HMMA (no FFMA, no cvt, no Wv LDS).
// Block: 32q x 32k tile, 8 warps (warp = 4 q rows x 32 k), grid (8,8,8).
// Masked tiles (k0 >= vl) skip all compute.
// ---------------------------------------------------------------------------
__global__ void __launch_bounds__(256) scores_kernel(
    const float* __restrict__ Wv, const int* __restrict__ vlens) {
    const int b = blockIdx.z;
    const int q0 = blockIdx.y * 32;
    const int k0 = blockIdx.x * 32;
    const int tid = threadIdx.x;
    const int vl = vlens[b];
    float* S = g_S + b * LQ * LK;

    if (k0 >= vl) {
        // whole tile masked
        const int qr = tid >> 3;
        const int k4 = tid & 7;
        const float4 mv = make_float4(MASK_VALUE, MASK_VALUE, MASK_VALUE, MASK_VALUE);
        *(float4*)&S[(q0 + qr) * LK + k0 + k4 * 4] = mv;
        return;
    }

    __shared__ uint32_t Qs[32 * SQ];   // [q][hp] half2, full K=256 h
    __shared__ uint32_t Ks[32 * SQ];   // [k][hp] half2
    __shared__ uint32_t Wv2s[128];     // Wv as half2 pairs

    if (tid < 128) {
        float2 wv = *(const float2*)&Wv[tid * 2];
        Wv2s[tid] = h2u(__floats2half2_rn(wv.x, wv.y));
    }

    // stage Q and K tiles (fp32 -> half2), coalesced float4 loads
    {
        const float* Qb = g_Qp + (b * LQ + q0) * HH;
        const float* Kb = g_Kp + (b * LK + k0) * HH;
        const int row = tid >> 3;   // 0..31
        const int c8 = tid & 7;     // 0..7
        #pragma unroll
        for (int j = 0; j < 8; j++) {
            const int c4 = j * 8 + c8;   // float4 index 0..63
            float4 qv = *(const float4*)&Qb[row * HH + c4 * 4];
            uint2 qp = make_uint2(h2u(__floats2half2_rn(qv.x, qv.y)),
                                  h2u(__floats2half2_rn(qv.z, qv.w)));
            *(uint2*)&Qs[row * SQ + c4 * 2] = qp;
            float4 kv = *(const float4*)&Kb[row * HH + c4 * 4];
            uint2 kp = make_uint2(h2u(__floats2half2_rn(kv.x, kv.y)),
                                  h2u(__floats2half2_rn(kv.z, kv.w)));
            *(uint2*)&Ks[row * SQ + c4 * 2] = kp;
        }
    }
    __syncthreads();

    const int lane = tid & 31;
    const int warp = tid >> 5;
    const int gid = lane >> 2;   // 0..7  -> k rows gid, gid+8 within 16-row group
    const int tig = lane & 3;    // 0..3  -> h pair positions

    const uint32_t* Qp0 = &Qs[(warp * 4) * SQ];

    float d[8][4];   // d[q*2+kh][...]
    #pragma unroll
    for (int i = 0; i < 8; i++)
        #pragma unroll
        for (int e = 0; e < 4; e++) d[i][e] = 0.f;

    #pragma unroll 4
    for (int c = 0; c < 16; c++) {
        const int hp0 = c * 8 + tig;
        const int hp1 = hp0 + 4;
        const uint32_t rb0 = Wv2s[hp0];
        const uint32_t rb1 = Wv2s[hp1];
        uint32_t kf[2][4];
        #pragma unroll
        for (int kh = 0; kh < 2; kh++) {
            const uint32_t* Kb0 = &Ks[(kh * 16 + gid) * SQ];
            kf[kh][0] = Kb0[hp0];
            kf[kh][1] = Kb0[hp1];
            kf[kh][2] = Kb0[8 * SQ + hp0];
            kf[kh][3] = Kb0[8 * SQ + hp1];
        }
        #pragma unroll
        for (int q = 0; q < 4; q++) {
            const uint32_t qv0 = Qp0[q * SQ + hp0];
            const uint32_t qv1 = Qp0[q * SQ + hp1];
            #pragma unroll
            for (int kh = 0; kh < 2; kh++) {
                uint32_t a0 = tanh2u(hadd2u(qv0, kf[kh][0]));  // row gid,   hp0
                uint32_t a1 = tanh2u(hadd2u(qv0, kf[kh][2]));  // row gid+8, hp0
                uint32_t a2 = tanh2u(hadd2u(qv1, kf[kh][1]));  // row gid,   hp1
                uint32_t a3 = tanh2u(hadd2u(qv1, kf[kh][3]));  // row gid+8, hp1
                mma16816(d[q * 2 + kh], a0, a1, a2, a3, rb0, rb1);
            }
        }
    }

    // All D columns are identical (B replicated); lane (gid,tig) holds rows
    // gid and gid+8 of every row-group. Distribute writes across tig.
    #pragma unroll
    for (int s = 0; s < 2; s++) {
        const int rg = tig + s * 4;
        const int qq = rg >> 1;
        const int kh = rg & 1;
        const int qrow = q0 + warp * 4 + qq;
        const int k1 = k0 + kh * 16 + gid;
        const int k2 = k1 + 8;
        S[qrow * LK + k1] = (k1 < vl) ? d[rg][0] : MASK_VALUE;
        S[qrow * LK + k2] = (k2 < vl) ? d[rg][2] : MASK_VALUE;
    }
}

// ---------------------------------------------------------------------------
// Softmax over axis=1 (QUERY axis) per (b, k) column — reference quirk.
// ---------------------------------------------------------------------------
__global__ void softmax_kernel() {
    const int b = blockIdx.y;
    const int tx = threadIdx.x & 31;
    const int ty = threadIdx.x >> 5;
    const int k = blockIdx.x * 32 + tx;
    float* S = g_S + b * LQ * LK;

    float vals[32];
    float m = -3.4e38f;
    #pragma unroll
    for (int i = 0; i < 32; i++) {
        vals[i] = S[(i * 8 + ty) * LK + k];
        m = fmaxf(m, vals[i]);
    }

    __shared__ float red[8][33];
    red[ty][tx] = m;
    __syncthreads();
    float M = red[0][tx];
    #pragma unroll
    for (int t = 1; t < 8; t++) M = fmaxf(M, red[t][tx]);
    __syncthreads();

    float s = 0.f;
    #pragma unroll
    for (int i = 0; i < 32; i++) {
        vals[i] = __expf(vals[i] - M);
        s += vals[i];
    }
    red[ty][tx] = s;
    __syncthreads();
    float SUM = 0.f;
    #pragma unroll
    for (int t = 0; t < 8; t++) SUM += red[t][tx];

    const float inv = 1.0f / SUM;
    #pragma unroll
    for (int i = 0; i < 32; i++)
        S[(i * 8 + ty) * LK + k] = vals[i] * inv;
}

// ---------------------------------------------------------------------------
// Output NN GEMM (tf32, R6/R9 structure): out[b][q][d] = sum_k A[q][k]*V[k][d]
// CTA 32q x 32d, 4 warps (2x2), warp tile 16x16; V staged transposed [d][k].
// grid (8, 8, 8) = 512 blocks.
// ---------------------------------------------------------------------------
__global__ void __launch_bounds__(128) out_kernel(
    const float* __restrict__ Vv, float* __restrict__ out) {
    const int b = blockIdx.z;
    const int q0 = blockIdx.y * 32;
    const int d0 = blockIdx.x * 32;
    const int tid = threadIdx.x;
    const int lane = tid & 31;
    const int warp = tid >> 5;
    const int gid = lane >> 2;
    const int tig = lane & 3;
    const int wq = (warp & 1) * 16;
    const int wn = (warp >> 1) * 16;

    const float* A = g_S + b * LQ * LK;
    const float* V = Vv + b * LK * DV;

    __shared__ uint32_t As[2][32 * TS];
    __shared__ uint32_t Vs[2][32 * VS];

    int srow[2], sc4[2];
    #pragma unroll
    for (int j = 0; j < 2; j++) {
        int idx = tid + j * 128;
        srow[j] = idx >> 3;
        sc4[j]  = idx & 7;
    }

    float d[2][4] = {};

    float4 av[2], vv[2];
    #pragma unroll
    for (int j = 0; j < 2; j++) {
        av[j] = *(const float4*)&A[(q0 + srow[j]) * LK + sc4[j] * 4];
        vv[j] = *(const float4*)&V[srow[j] * DV + d0 + sc4[j] * 4];
    }

    for (int c = 0; c < 8; c++) {
        uint32_t* AB = As[c & 1];
        uint32_t* VB = Vs[c & 1];
        #pragma unroll
        for (int j = 0; j < 2; j++) {
            uint32_t* pa = &AB[srow[j] * TS + sc4[j] * 4];
            pa[0] = f2tf(av[j].x); pa[1] = f2tf(av[j].y);
            pa[2] = f2tf(av[j].z); pa[3] = f2tf(av[j].w);
            const int dc = sc4[j] * 4;
            VB[(dc + 0) * VS + srow[j]] = f2tf(vv[j].x);
            VB[(dc + 1) * VS + srow[j]] = f2tf(vv[j].y);
            VB[(dc + 2) * VS + srow[j]] = f2tf(vv[j].z);
            VB[(dc + 3) * VS + srow[j]] = f2tf(vv[j].w);
        }
        __syncthreads();

        if (c < 7) {
            const int k0 = (c + 1) * 32;
            #pragma unroll
            for (int j = 0; j < 2; j++) {
                av[j] = *(const float4*)&A[(q0 + srow[j]) * LK + k0 + sc4[j] * 4];
                vv[j] = *(const float4*)&V[(k0 + srow[j]) * DV + d0 + sc4[j] * 4];
            }
        }

        #pragma unroll
        for (int ks = 0; ks < 4; ks++) {
            const int kk = ks * 8;
            uint32_t a[4], bfr[2][2];
            const int r = wq + gid;
            a[0] = AB[r * TS + kk + tig];
            a[1] = AB[(r + 8) * TS + kk + tig];
            a[2] = AB[r * TS + kk + tig + 4];
            a[3] = AB[(r + 8) * TS + kk + tig + 4];
            #pragma unroll
            for (int jn = 0; jn < 2; jn++) {
                int n = wn + jn * 8 + gid;
                bfr[jn][0] = VB[n * VS + kk + tig];
                bfr[jn][1] = VB[n * VS + kk + tig + 4];
            }
            mma8(d[0], a, bfr[0]);
            mma8(d[1], a, bfr[1]);
        }
    }

    float* O = out + b * LQ * DV;
    #pragma unroll
    for (int jn = 0; jn < 2; jn++) {
        int row = q0 + wq + gid;
        int col = d0 + wn + jn * 8 + tig * 2;
        *(float2*)&O[row * DV + col] = make_float2(d[jn][0], d[jn][1]);
        *(float2*)&O[(row + 8) * DV + col] = make_float2(d[jn][2], d[jn][3]);
    }
}

extern "C" void kernel_launch(void* const* d_in, const int* in_sizes, int n_in,
                              void* d_out, int out_size) {
    const float* queries    = (const float*)d_in[0];
    const float* keyes      = (const float*)d_in[1];
    const float* values     = (const float*)d_in[2];
    const int*   valid_lens = (const int*)d_in[3];
    const float* W_q        = (const float*)d_in[4];
    const float* W_k        = (const float*)d_in[5];
    const float* W_v        = (const float*)d_in[6];
    float* out = (float*)d_out;

    proj_kernel<<<dim3(4, 32, 2), 128>>>(queries, W_q, keyes, W_k);
    scores_kernel<<<dim3(8, 8, 8), 256>>>(W_v, valid_lens);
    softmax_kernel<<<dim3(8, 8), 256>>>();
    out_kernel<<<dim3(8, 8, 8), 128>>>(values, out);
}